// round 13
// baseline (speedup 1.0000x reference)
#include <cuda_runtime.h>
#include <cstdint>

#define TPB 128
#define RG_BYTES  (TPB * 19 * 4)
#define COV_BYTES (TPB * 9 * 4)
#define HAR_BYTES (TPB * 12 * 4)
#define BUF_FLOATS (TPB * 21)

__global__ void __launch_bounds__(TPB, 10)
mono_gaussian_adapter_kernel(
    const float* __restrict__ ext,        // (B,1,4,4)
    const float* __restrict__ intr,       // (B,1,3,3)
    const float* __restrict__ coords,     // (B,N,2)
    const float* __restrict__ depths,     // (B,N)
    const float* __restrict__ opac,       // (B,N)
    const float* __restrict__ rg,         // (B,N,19)
    const unsigned int* __restrict__ hptr,
    const unsigned int* __restrict__ wptr,
    float* __restrict__ out,
    int N, int BN, int ntiles, int tpbatch)
{
    // Two pipeline buffers: input rg (19T floats) lands via cp.async.bulk; after
    // consumption the same buffer stages cov[0,9T) har[9T,21T) for the bulk flush.
    __shared__ __align__(16) float buf[2][BUF_FLOATS];
    __shared__ float cam[22];   // c2w[0..8], t[9..11], Kinv[12..20], mult[21]
    __shared__ __align__(8) unsigned long long mbar[2];

    const int tid = threadIdx.x;
    const int G   = gridDim.x;

    const uint32_t sb0  = (uint32_t)__cvta_generic_to_shared(buf[0]);
    const uint32_t sb1  = (uint32_t)__cvta_generic_to_shared(buf[1]);
    const uint32_t smb0 = (uint32_t)__cvta_generic_to_shared(&mbar[0]);
    const uint32_t smb1 = (uint32_t)__cvta_generic_to_shared(&mbar[1]);

    // ---- init mbarriers + prologue prefetch (tile for iteration 0) ----
    if (tid == 0) {
        asm volatile("mbarrier.init.shared.b64 [%0], 1;" :: "r"(smb0) : "memory");
        asm volatile("mbarrier.init.shared.b64 [%0], 1;" :: "r"(smb1) : "memory");
        asm volatile("fence.proxy.async.shared::cta;" ::: "memory");
        int t = blockIdx.x;
        if (t < ntiles) {
            int b0 = t / tpbatch, t0 = (t - b0 * tpbatch) * TPB;
            if (t0 + TPB <= N) {
                asm volatile("mbarrier.arrive.expect_tx.shared.b64 _, [%0], %1;"
                             :: "r"(smb0), "r"((uint32_t)RG_BYTES) : "memory");
                asm volatile("cp.async.bulk.shared::cta.global.mbarrier::complete_tx::bytes "
                             "[%0], [%1], %2, [%3];"
                             :: "r"(sb0), "l"(rg + (size_t)(b0 * N + t0) * 19),
                                "r"((uint32_t)RG_BYTES), "r"(smb0) : "memory");
            }
        }
    }
    __syncthreads();   // mbar init visible to all waiters

    float* means_o = out;                          // BN*3
    float* cov_o   = out + (size_t)BN * 3;         // BN*9
    float* har_o   = out + (size_t)BN * 12;        // BN*12
    float* op_o    = out + (size_t)BN * 24;        // BN*1
    float* sc_o    = out + (size_t)BN * 25;        // BN*3
    float* rot_o   = out + (size_t)BN * 28;        // BN*4

    int phase0 = 0, phase1 = 0;
    int it = 0;
    for (int tile = blockIdx.x; tile < ntiles; tile += G, it++) {
        const int cur = it & 1;
        const uint32_t sbc  = cur ? sb1 : sb0;
        const uint32_t smbc = cur ? smb1 : smb0;
        float* bufc = cur ? buf[1] : buf[0];

        const int b    = tile / tpbatch;
        const int t0   = (tile - b * tpbatch) * TPB;
        const int idx0 = b * N + t0;
        const int idx  = idx0 + tid;
        const bool fullt = (t0 + TPB) <= N;
        const bool live  = (t0 + tid) < N;

        if (tid == 0) {
            // ---- prefetch NEXT tile into the other buffer (overlaps this tile's compute) ----
            int nt = tile + G;
            if (nt < ntiles) {
                int nb = nt / tpbatch, n0 = (nt - nb * tpbatch) * TPB;
                if (n0 + TPB <= N) {
                    const uint32_t sbn  = cur ? sb0 : sb1;
                    const uint32_t smbn = cur ? smb0 : smb1;
                    // other buffer's TMA-out reads must be done before new input lands
                    asm volatile("cp.async.bulk.wait_group.read 0;" ::: "memory");
                    asm volatile("mbarrier.arrive.expect_tx.shared.b64 _, [%0], %1;"
                                 :: "r"(smbn), "r"((uint32_t)RG_BYTES) : "memory");
                    asm volatile("cp.async.bulk.shared::cta.global.mbarrier::complete_tx::bytes "
                                 "[%0], [%1], %2, [%3];"
                                 :: "r"(sbn), "l"(rg + (size_t)(nb * N + n0) * 19),
                                    "r"((uint32_t)RG_BYTES), "r"(smbn) : "memory");
                }
            }
            // ---- cam for this tile's batch ----
            const float* E = ext + b * 16;
            const float* K = intr + b * 9;
#pragma unroll
            for (int i = 0; i < 3; i++) {
                cam[i * 3 + 0] = E[i * 4 + 0];
                cam[i * 3 + 1] = E[i * 4 + 1];
                cam[i * 3 + 2] = E[i * 4 + 2];
                cam[9 + i]     = E[i * 4 + 3];
            }
            float k00 = K[0], k01 = K[1], k02 = K[2];
            float k10 = K[3], k11 = K[4], k12 = K[5];
            float k20 = K[6], k21 = K[7], k22 = K[8];
            float det = k00 * (k11 * k22 - k12 * k21)
                      - k01 * (k10 * k22 - k12 * k20)
                      + k02 * (k10 * k21 - k11 * k20);
            float id = 1.0f / det;
            cam[12] = (k11 * k22 - k12 * k21) * id;
            cam[13] = (k02 * k21 - k01 * k22) * id;
            cam[14] = (k01 * k12 - k02 * k11) * id;
            cam[15] = (k12 * k20 - k10 * k22) * id;
            cam[16] = (k00 * k22 - k02 * k20) * id;
            cam[17] = (k02 * k10 - k00 * k12) * id;
            cam[18] = (k10 * k21 - k11 * k20) * id;
            cam[19] = (k01 * k20 - k00 * k21) * id;
            cam[20] = (k00 * k11 - k01 * k10) * id;
            unsigned hv = hptr[0], wv = wptr[0];
            float hf = (hv < 100000u) ? (float)hv : __uint_as_float(hv);
            float wf = (wv < 100000u) ? (float)wv : __uint_as_float(wv);
            float px = 1.0f / wf, py = 1.0f / hf;
            float det2 = k00 * k11 - k01 * k10;
            cam[21] = 0.1f * ((k11 * px - k01 * py) + (-k10 * px + k00 * py)) / det2;
        }
        __syncthreads();   // cam ready

        // ---- per-thread scalar inputs + rg-independent outputs (overlap DMA wait) ----
        float2 uv = make_float2(0.f, 0.f);
        float depth = 0.f, op = 0.f;
        if (live) {
            uv    = ((const float2*)coords)[idx];
            depth = depths[idx];
            op    = opac[idx];

            __stcs(op_o + idx, op);
            float d0 = cam[12] * uv.x + cam[13] * uv.y + cam[14];
            float d1 = cam[15] * uv.x + cam[16] * uv.y + cam[17];
            float d2 = cam[18] * uv.x + cam[19] * uv.y + cam[20];
            float rn = rsqrtf(d0 * d0 + d1 * d1 + d2 * d2);
            d0 *= rn; d1 *= rn; d2 *= rn;
            __stcs(means_o + (size_t)idx * 3 + 0,
                   cam[9]  + (cam[0] * d0 + cam[1] * d1 + cam[2] * d2) * depth);
            __stcs(means_o + (size_t)idx * 3 + 1,
                   cam[10] + (cam[3] * d0 + cam[4] * d1 + cam[5] * d2) * depth);
            __stcs(means_o + (size_t)idx * 3 + 2,
                   cam[11] + (cam[6] * d0 + cam[7] * d1 + cam[8] * d2) * depth);
        }

        // ---- wait for this tile's rg (prefetched last iteration -> usually no stall) ----
        if (fullt) {
            int ph = cur ? phase1 : phase0;
            asm volatile(
                "{\n\t.reg .pred p;\n\t"
                "WAIT_%=:\n\t"
                "mbarrier.try_wait.parity.acquire.cta.shared::cta.b64 p, [%0], %1, 0x989680;\n\t"
                "@p bra DONE_%=;\n\t"
                "bra WAIT_%=;\n\t"
                "DONE_%=:\n\t}"
                :: "r"(smbc), "r"((uint32_t)ph) : "memory");
            if (cur) phase1 ^= 1; else phase0 ^= 1;
        }

        // ---- consume rg ----
        const float* grow_s = bufc + tid * 19;
        const float* grow_g = rg + (size_t)idx * 19;
        float g0, g1, g2, qw, qx, qy, qz;
        if (fullt) {
            g0 = grow_s[0]; g1 = grow_s[1]; g2 = grow_s[2];
            qw = grow_s[3]; qx = grow_s[4]; qy = grow_s[5]; qz = grow_s[6];
        } else if (live) {
            g0 = grow_g[0]; g1 = grow_g[1]; g2 = grow_g[2];
            qw = grow_g[3]; qx = grow_g[4]; qy = grow_g[5]; qz = grow_g[6];
        } else {
            g0 = g1 = g2 = 0.f; qw = 1.f; qx = qy = qz = 0.f;
        }

        float dm = depth * cam[21];
        float sc0 = (0.5f + 14.5f / (1.0f + __expf(-g0))) * dm;
        float sc1 = (0.5f + 14.5f / (1.0f + __expf(-g1))) * dm;
        float sc2 = (0.5f + 14.5f / (1.0f + __expf(-g2))) * dm;

        float qn = sqrtf(qw * qw + qx * qx + qy * qy + qz * qz) + 1e-8f;
        float qinv = 1.0f / qn;
        qw *= qinv; qx *= qinv; qy *= qinv; qz *= qinv;

        float har[12];
        {
            const int pr[3] = {1, 2, 0};
#pragma unroll
            for (int c = 0; c < 3; c++) {
                float h0, s1, s2, s3;
                if (fullt) {
                    h0 = grow_s[7 + c * 4 + 0];
                    s1 = grow_s[7 + c * 4 + 1] * 0.025f;
                    s2 = grow_s[7 + c * 4 + 2] * 0.025f;
                    s3 = grow_s[7 + c * 4 + 3] * 0.025f;
                } else if (live) {
                    h0 = grow_g[7 + c * 4 + 0];
                    s1 = grow_g[7 + c * 4 + 1] * 0.025f;
                    s2 = grow_g[7 + c * 4 + 2] * 0.025f;
                    s3 = grow_g[7 + c * 4 + 3] * 0.025f;
                } else {
                    h0 = s1 = s2 = s3 = 0.f;
                }
                har[c * 4 + 0] = h0;
#pragma unroll
                for (int i = 0; i < 3; i++) {
                    int ri = pr[i];
                    har[c * 4 + 1 + i] = cam[ri * 3 + 1] * s1
                                       + cam[ri * 3 + 2] * s2
                                       + cam[ri * 3 + 0] * s3;
                }
            }
        }

        float R[9];
        R[0] = 1.f - 2.f * (qy * qy + qz * qz);
        R[1] = 2.f * (qx * qy - qw * qz);
        R[2] = 2.f * (qx * qz + qw * qy);
        R[3] = 2.f * (qx * qy + qw * qz);
        R[4] = 1.f - 2.f * (qx * qx + qz * qz);
        R[5] = 2.f * (qy * qz - qw * qx);
        R[6] = 2.f * (qx * qz - qw * qy);
        R[7] = 2.f * (qy * qz + qw * qx);
        R[8] = 1.f - 2.f * (qx * qx + qy * qy);

        float T[9];
#pragma unroll
        for (int i = 0; i < 3; i++) {
            T[i * 3 + 0] = (cam[i * 3 + 0] * R[0] + cam[i * 3 + 1] * R[3]
                          + cam[i * 3 + 2] * R[6]) * sc0;
            T[i * 3 + 1] = (cam[i * 3 + 0] * R[1] + cam[i * 3 + 1] * R[4]
                          + cam[i * 3 + 2] * R[7]) * sc1;
            T[i * 3 + 2] = (cam[i * 3 + 0] * R[2] + cam[i * 3 + 1] * R[5]
                          + cam[i * 3 + 2] * R[8]) * sc2;
        }
        float cov[9];
#pragma unroll
        for (int i = 0; i < 3; i++)
#pragma unroll
            for (int j = 0; j <= i; j++) {
                float v = T[i * 3 + 0] * T[j * 3 + 0]
                        + T[i * 3 + 1] * T[j * 3 + 1]
                        + T[i * 3 + 2] * T[j * 3 + 2];
                cov[i * 3 + j] = v;
                cov[j * 3 + i] = v;
            }

        __syncthreads();   // consumption + all cam reads complete

        // direct streaming stores: rotations, scales
        if (live) {
            __stcs((float4*)rot_o + idx, make_float4(qw, qx, qy, qz));
            __stcs(sc_o + (size_t)idx * 3 + 0, sc0);
            __stcs(sc_o + (size_t)idx * 3 + 1, sc1);
            __stcs(sc_o + (size_t)idx * 3 + 2, sc2);
        }

        if (fullt) {
            // stage cov (scalar stride 9, odd -> conflict-free)
#pragma unroll
            for (int i = 0; i < 9; i++) bufc[tid * 9 + i] = cov[i];
            // stage har (STS.128, float4-stride 3 -> conflict-free)
            {
                float4* h4 = (float4*)(bufc + 9 * TPB);
#pragma unroll
                for (int c = 0; c < 3; c++)
                    h4[tid * 3 + c] = make_float4(har[c * 4 + 0], har[c * 4 + 1],
                                                  har[c * 4 + 2], har[c * 4 + 3]);
            }
            __syncthreads();   // staging complete

            if (tid == 0) {
                asm volatile("fence.proxy.async.shared::cta;" ::: "memory");
                asm volatile("cp.async.bulk.global.shared::cta.bulk_group [%0], [%1], %2;"
                             :: "l"(cov_o + (size_t)idx0 * 9), "r"(sbc),
                                "r"((uint32_t)COV_BYTES) : "memory");
                asm volatile("cp.async.bulk.global.shared::cta.bulk_group [%0], [%1], %2;"
                             :: "l"(har_o + (size_t)idx0 * 12),
                                "r"(sbc + (uint32_t)COV_BYTES),
                                "r"((uint32_t)HAR_BYTES) : "memory");
                asm volatile("cp.async.bulk.commit_group;" ::: "memory");
            }
        } else if (live) {
#pragma unroll
            for (int i = 0; i < 9; i++)  __stcs(cov_o + (size_t)idx * 9 + i, cov[i]);
#pragma unroll
            for (int i = 0; i < 12; i++) __stcs(har_o + (size_t)idx * 12 + i, har[i]);
        }
    }

    // keep CTA (and its smem) alive until the final TMA-out's smem reads complete
    if (tid == 0)
        asm volatile("cp.async.bulk.wait_group.read 0;" ::: "memory");
}

extern "C" void kernel_launch(void* const* d_in, const int* in_sizes, int n_in,
                              void* d_out, int out_size)
{
    const float* ext    = (const float*)d_in[0];
    const float* intr   = (const float*)d_in[1];
    const float* coords = (const float*)d_in[2];
    const float* depths = (const float*)d_in[3];
    const float* opac   = (const float*)d_in[4];
    const float* rg     = (const float*)d_in[5];
    const unsigned int* hptr = (const unsigned int*)d_in[6];
    const unsigned int* wptr = (const unsigned int*)d_in[7];
    float* out = (float*)d_out;

    const int B = in_sizes[0] / 16;            // extrinsics: B*1*4*4
    const int N = in_sizes[3] / B;             // depths: B*N
    const int BN = B * N;
    const int tpbatch = (N + TPB - 1) / TPB;   // tiles per batch
    const int ntiles  = B * tpbatch;

    int G = 148 * 10;                          // one resident wave at 10 blocks/SM
    if (G > ntiles) G = ntiles;

    mono_gaussian_adapter_kernel<<<G, TPB>>>(
        ext, intr, coords, depths, opac, rg, hptr, wptr, out,
        N, BN, ntiles, tpbatch);
}

// round 14
// speedup vs baseline: 1.0317x; 1.0317x over previous
#include <cuda_runtime.h>
#include <cstdint>

#define TPB 128
#define RG_BYTES  (TPB * 19 * 4)
#define COV_BYTES (TPB * 9 * 4)
#define HAR_BYTES (TPB * 12 * 4)
#define BUF_FLOATS (TPB * 21)

__global__ void __launch_bounds__(TPB, 10)
mono_gaussian_adapter_kernel(
    const float* __restrict__ ext,        // (B,1,4,4)
    const float* __restrict__ intr,       // (B,1,3,3)
    const float* __restrict__ coords,     // (B,N,2)
    const float* __restrict__ depths,     // (B,N)
    const float* __restrict__ opac,       // (B,N)
    const float* __restrict__ rg,         // (B,N,19)
    const unsigned int* __restrict__ hptr,
    const unsigned int* __restrict__ wptr,
    float* __restrict__ out,
    int N)
{
    // Two buffers: each receives one rg tile via cp.async.bulk (both issued at
    // block start), then is reused to stage that tile's cov[0,9T) har[9T,21T).
    __shared__ __align__(16) float buf[2][BUF_FLOATS];
    __shared__ float cam[22];   // c2w[0..8], t[9..11], Kinv[12..20], mult[21]
    __shared__ __align__(8) unsigned long long mbar[2];

    const int b   = blockIdx.y;
    const int tid = threadIdx.x;
    const int base = blockIdx.x * (2 * TPB);        // first element of tile A
    const int BN  = (int)gridDim.y * N;

    const uint32_t sb[2]  = { (uint32_t)__cvta_generic_to_shared(buf[0]),
                              (uint32_t)__cvta_generic_to_shared(buf[1]) };
    const uint32_t smb[2] = { (uint32_t)__cvta_generic_to_shared(&mbar[0]),
                              (uint32_t)__cvta_generic_to_shared(&mbar[1]) };

    const bool fullA = (base + TPB)     <= N;
    const bool fullB = (base + 2 * TPB) <= N;

    // ---- issue BOTH input DMAs immediately ----
    if (tid == 0) {
        asm volatile("mbarrier.init.shared.b64 [%0], 1;" :: "r"(smb[0]) : "memory");
        asm volatile("mbarrier.init.shared.b64 [%0], 1;" :: "r"(smb[1]) : "memory");
        asm volatile("fence.proxy.async.shared::cta;" ::: "memory");
        if (fullA) {
            asm volatile("mbarrier.arrive.expect_tx.shared.b64 _, [%0], %1;"
                         :: "r"(smb[0]), "r"((uint32_t)RG_BYTES) : "memory");
            asm volatile("cp.async.bulk.shared::cta.global.mbarrier::complete_tx::bytes "
                         "[%0], [%1], %2, [%3];"
                         :: "r"(sb[0]), "l"(rg + (size_t)(b * N + base) * 19),
                            "r"((uint32_t)RG_BYTES), "r"(smb[0]) : "memory");
        }
        if (fullB) {
            asm volatile("mbarrier.arrive.expect_tx.shared.b64 _, [%0], %1;"
                         :: "r"(smb[1]), "r"((uint32_t)RG_BYTES) : "memory");
            asm volatile("cp.async.bulk.shared::cta.global.mbarrier::complete_tx::bytes "
                         "[%0], [%1], %2, [%3];"
                         :: "r"(sb[1]), "l"(rg + (size_t)(b * N + base + TPB) * 19),
                            "r"((uint32_t)RG_BYTES), "r"(smb[1]) : "memory");
        }

        // ---- cam (overlaps DMA) ----
        const float* E = ext + b * 16;
        const float* K = intr + b * 9;
#pragma unroll
        for (int i = 0; i < 3; i++) {
            cam[i * 3 + 0] = E[i * 4 + 0];
            cam[i * 3 + 1] = E[i * 4 + 1];
            cam[i * 3 + 2] = E[i * 4 + 2];
            cam[9 + i]     = E[i * 4 + 3];
        }
        float k00 = K[0], k01 = K[1], k02 = K[2];
        float k10 = K[3], k11 = K[4], k12 = K[5];
        float k20 = K[6], k21 = K[7], k22 = K[8];
        float det = k00 * (k11 * k22 - k12 * k21)
                  - k01 * (k10 * k22 - k12 * k20)
                  + k02 * (k10 * k21 - k11 * k20);
        float id = 1.0f / det;
        cam[12] = (k11 * k22 - k12 * k21) * id;
        cam[13] = (k02 * k21 - k01 * k22) * id;
        cam[14] = (k01 * k12 - k02 * k11) * id;
        cam[15] = (k12 * k20 - k10 * k22) * id;
        cam[16] = (k00 * k22 - k02 * k20) * id;
        cam[17] = (k02 * k10 - k00 * k12) * id;
        cam[18] = (k10 * k21 - k11 * k20) * id;
        cam[19] = (k01 * k20 - k00 * k21) * id;
        cam[20] = (k00 * k11 - k01 * k10) * id;
        unsigned hv = hptr[0], wv = wptr[0];
        float hf = (hv < 100000u) ? (float)hv : __uint_as_float(hv);
        float wf = (wv < 100000u) ? (float)wv : __uint_as_float(wv);
        float px = 1.0f / wf, py = 1.0f / hf;
        float det2 = k00 * k11 - k01 * k10;
        cam[21] = 0.1f * ((k11 * px - k01 * py) + (-k10 * px + k00 * py)) / det2;
    }
    __syncthreads();   // cam + mbar inits visible

    float* means_o = out;                          // BN*3
    float* cov_o   = out + (size_t)BN * 3;         // BN*9
    float* har_o   = out + (size_t)BN * 12;        // BN*12
    float* op_o    = out + (size_t)BN * 24;        // BN*1
    float* sc_o    = out + (size_t)BN * 25;        // BN*3
    float* rot_o   = out + (size_t)BN * 28;        // BN*4

#pragma unroll 1
    for (int half = 0; half < 2; half++) {
        const int t0    = base + half * TPB;
        const int idx0  = b * N + t0;
        const int idx   = idx0 + tid;
        const bool fullt = half ? fullB : fullA;
        const bool live  = (t0 + tid) < N;
        float* bufc = buf[half];

        // ---- per-thread scalar inputs + rg-independent outputs (overlap DMA) ----
        float2 uv = make_float2(0.f, 0.f);
        float depth = 0.f, op = 0.f;
        if (live) {
            uv    = ((const float2*)coords)[idx];
            depth = depths[idx];
            op    = opac[idx];

            __stcs(op_o + idx, op);
            float d0 = cam[12] * uv.x + cam[13] * uv.y + cam[14];
            float d1 = cam[15] * uv.x + cam[16] * uv.y + cam[17];
            float d2 = cam[18] * uv.x + cam[19] * uv.y + cam[20];
            float rn = rsqrtf(d0 * d0 + d1 * d1 + d2 * d2);
            d0 *= rn; d1 *= rn; d2 *= rn;
            __stcs(means_o + (size_t)idx * 3 + 0,
                   cam[9]  + (cam[0] * d0 + cam[1] * d1 + cam[2] * d2) * depth);
            __stcs(means_o + (size_t)idx * 3 + 1,
                   cam[10] + (cam[3] * d0 + cam[4] * d1 + cam[5] * d2) * depth);
            __stcs(means_o + (size_t)idx * 3 + 2,
                   cam[11] + (cam[6] * d0 + cam[7] * d1 + cam[8] * d2) * depth);
        }

        // ---- wait for this tile's rg (tile B: fully hidden behind tile A) ----
        if (fullt) {
            asm volatile(
                "{\n\t.reg .pred p;\n\t"
                "WAIT_%=:\n\t"
                "mbarrier.try_wait.parity.acquire.cta.shared::cta.b64 p, [%0], %1, 0x989680;\n\t"
                "@p bra DONE_%=;\n\t"
                "bra WAIT_%=;\n\t"
                "DONE_%=:\n\t}"
                :: "r"(smb[half]), "r"(0u) : "memory");
        }

        // ---- consume rg ----
        const float* grow_s = bufc + tid * 19;
        const float* grow_g = rg + (size_t)idx * 19;
        float g0, g1, g2, qw, qx, qy, qz;
        if (fullt) {
            g0 = grow_s[0]; g1 = grow_s[1]; g2 = grow_s[2];
            qw = grow_s[3]; qx = grow_s[4]; qy = grow_s[5]; qz = grow_s[6];
        } else if (live) {
            g0 = grow_g[0]; g1 = grow_g[1]; g2 = grow_g[2];
            qw = grow_g[3]; qx = grow_g[4]; qy = grow_g[5]; qz = grow_g[6];
        } else {
            g0 = g1 = g2 = 0.f; qw = 1.f; qx = qy = qz = 0.f;
        }

        float dm = depth * cam[21];
        float sc0 = (0.5f + 14.5f / (1.0f + __expf(-g0))) * dm;
        float sc1 = (0.5f + 14.5f / (1.0f + __expf(-g1))) * dm;
        float sc2 = (0.5f + 14.5f / (1.0f + __expf(-g2))) * dm;

        float qn = sqrtf(qw * qw + qx * qx + qy * qy + qz * qz) + 1e-8f;
        float qinv = 1.0f / qn;
        qw *= qinv; qx *= qinv; qy *= qinv; qz *= qinv;

        float har[12];
        {
            const int pr[3] = {1, 2, 0};
#pragma unroll
            for (int c = 0; c < 3; c++) {
                float h0, s1, s2, s3;
                if (fullt) {
                    h0 = grow_s[7 + c * 4 + 0];
                    s1 = grow_s[7 + c * 4 + 1] * 0.025f;
                    s2 = grow_s[7 + c * 4 + 2] * 0.025f;
                    s3 = grow_s[7 + c * 4 + 3] * 0.025f;
                } else if (live) {
                    h0 = grow_g[7 + c * 4 + 0];
                    s1 = grow_g[7 + c * 4 + 1] * 0.025f;
                    s2 = grow_g[7 + c * 4 + 2] * 0.025f;
                    s3 = grow_g[7 + c * 4 + 3] * 0.025f;
                } else {
                    h0 = s1 = s2 = s3 = 0.f;
                }
                har[c * 4 + 0] = h0;
#pragma unroll
                for (int i = 0; i < 3; i++) {
                    int ri = pr[i];
                    har[c * 4 + 1 + i] = cam[ri * 3 + 1] * s1
                                       + cam[ri * 3 + 2] * s2
                                       + cam[ri * 3 + 0] * s3;
                }
            }
        }

        if (live) {
            __stcs((float4*)rot_o + idx, make_float4(qw, qx, qy, qz));
            __stcs(sc_o + (size_t)idx * 3 + 0, sc0);
            __stcs(sc_o + (size_t)idx * 3 + 1, sc1);
            __stcs(sc_o + (size_t)idx * 3 + 2, sc2);
        }

        float R[9];
        R[0] = 1.f - 2.f * (qy * qy + qz * qz);
        R[1] = 2.f * (qx * qy - qw * qz);
        R[2] = 2.f * (qx * qz + qw * qy);
        R[3] = 2.f * (qx * qy + qw * qz);
        R[4] = 1.f - 2.f * (qx * qx + qz * qz);
        R[5] = 2.f * (qy * qz - qw * qx);
        R[6] = 2.f * (qx * qz - qw * qy);
        R[7] = 2.f * (qy * qz + qw * qx);
        R[8] = 1.f - 2.f * (qx * qx + qy * qy);

        float T[9];
#pragma unroll
        for (int i = 0; i < 3; i++) {
            T[i * 3 + 0] = (cam[i * 3 + 0] * R[0] + cam[i * 3 + 1] * R[3]
                          + cam[i * 3 + 2] * R[6]) * sc0;
            T[i * 3 + 1] = (cam[i * 3 + 0] * R[1] + cam[i * 3 + 1] * R[4]
                          + cam[i * 3 + 2] * R[7]) * sc1;
            T[i * 3 + 2] = (cam[i * 3 + 0] * R[2] + cam[i * 3 + 1] * R[5]
                          + cam[i * 3 + 2] * R[8]) * sc2;
        }
        float cov[9];
#pragma unroll
        for (int i = 0; i < 3; i++)
#pragma unroll
            for (int j = 0; j <= i; j++) {
                float v = T[i * 3 + 0] * T[j * 3 + 0]
                        + T[i * 3 + 1] * T[j * 3 + 1]
                        + T[i * 3 + 2] * T[j * 3 + 2];
                cov[i * 3 + j] = v;
                cov[j * 3 + i] = v;
            }

        if (fullt) {
            __syncthreads();   // all smem input reads of THIS buffer complete

            // stage cov (scalar stride 9, odd -> conflict-free)
#pragma unroll
            for (int i = 0; i < 9; i++) bufc[tid * 9 + i] = cov[i];
            // stage har (STS.128, float4-stride 3 -> conflict-free)
            {
                float4* h4 = (float4*)(bufc + 9 * TPB);
#pragma unroll
                for (int c = 0; c < 3; c++)
                    h4[tid * 3 + c] = make_float4(har[c * 4 + 0], har[c * 4 + 1],
                                                  har[c * 4 + 2], har[c * 4 + 3]);
            }
            __syncthreads();   // staging complete

            if (tid == 0) {
                asm volatile("fence.proxy.async.shared::cta;" ::: "memory");
                asm volatile("cp.async.bulk.global.shared::cta.bulk_group [%0], [%1], %2;"
                             :: "l"(cov_o + (size_t)idx0 * 9), "r"(sb[half]),
                                "r"((uint32_t)COV_BYTES) : "memory");
                asm volatile("cp.async.bulk.global.shared::cta.bulk_group [%0], [%1], %2;"
                             :: "l"(har_o + (size_t)idx0 * 12),
                                "r"(sb[half] + (uint32_t)COV_BYTES),
                                "r"((uint32_t)HAR_BYTES) : "memory");
                asm volatile("cp.async.bulk.commit_group;" ::: "memory");
            }
        } else if (live) {
#pragma unroll
            for (int i = 0; i < 9; i++)  __stcs(cov_o + (size_t)idx * 9 + i, cov[i]);
#pragma unroll
            for (int i = 0; i < 12; i++) __stcs(har_o + (size_t)idx * 12 + i, har[i]);
        }
    }

    // keep CTA (and its smem) alive until both TMA-out groups' smem reads complete
    if (tid == 0)
        asm volatile("cp.async.bulk.wait_group.read 0;" ::: "memory");
}

extern "C" void kernel_launch(void* const* d_in, const int* in_sizes, int n_in,
                              void* d_out, int out_size)
{
    const float* ext    = (const float*)d_in[0];
    const float* intr   = (const float*)d_in[1];
    const float* coords = (const float*)d_in[2];
    const float* depths = (const float*)d_in[3];
    const float* opac   = (const float*)d_in[4];
    const float* rg     = (const float*)d_in[5];
    const unsigned int* hptr = (const unsigned int*)d_in[6];
    const unsigned int* wptr = (const unsigned int*)d_in[7];
    float* out = (float*)d_out;

    const int B = in_sizes[0] / 16;            // extrinsics: B*1*4*4
    const int N = in_sizes[3] / B;             // depths: B*N

    dim3 grid((N + 2 * TPB - 1) / (2 * TPB), B);
    mono_gaussian_adapter_kernel<<<grid, TPB>>>(
        ext, intr, coords, depths, opac, rg, hptr, wptr, out, N);
}

// round 15
// speedup vs baseline: 1.0613x; 1.0287x over previous
#include <cuda_runtime.h>
#include <cstdint>

#define TPB 128
#define RG_BYTES (TPB * 19 * 4)
#define COV_BYTES (TPB * 9 * 4)
#define HAR_BYTES (TPB * 12 * 4)

struct CamParams {
    float c2w[9];
    float t[3];
    float Kinv[9];
    float mult;
};

__global__ void __launch_bounds__(TPB, 12)
mono_gaussian_adapter_kernel(
    const float* __restrict__ ext,        // (B,1,4,4)
    const float* __restrict__ intr,       // (B,1,3,3)
    const float* __restrict__ coords,     // (B,N,2)
    const float* __restrict__ depths,     // (B,N)
    const float* __restrict__ opac,       // (B,N)
    const float* __restrict__ rg,         // (B,N,19)
    const unsigned int* __restrict__ hptr,
    const unsigned int* __restrict__ wptr,
    float* __restrict__ out,
    int N)
{
    // Staging buffer: input rg (19T floats) via cp.async.bulk in, reused for
    // outputs cov[0,9T) har[9T,21T) flushed via cp.async.bulk out.
    __shared__ __align__(16) float buf[TPB * 21];
    __shared__ CamParams cam;
    __shared__ __align__(8) unsigned long long mbar;

    const int b   = blockIdx.y;
    const int tid = threadIdx.x;

    const int n    = blockIdx.x * TPB + tid;
    const int idx0 = b * N + blockIdx.x * TPB;
    const int idx  = idx0 + tid;
    const int BN   = (int)gridDim.y * N;
    const bool full = (blockIdx.x * TPB + TPB) <= N;
    const bool live = n < N;

    const uint32_t smem_buf  = (uint32_t)__cvta_generic_to_shared(buf);
    const uint32_t smem_mbar = (uint32_t)__cvta_generic_to_shared(&mbar);

    // ---- kick off bulk DMA of the rg tile ASAP (full blocks) ----
    if (full && tid == 0) {
        asm volatile("mbarrier.init.shared.b64 [%0], 1;" :: "r"(smem_mbar) : "memory");
        asm volatile("fence.proxy.async.shared::cta;" ::: "memory");
        asm volatile("mbarrier.arrive.expect_tx.shared.b64 _, [%0], %1;"
                     :: "r"(smem_mbar), "r"((uint32_t)RG_BYTES) : "memory");
        asm volatile("cp.async.bulk.shared::cta.global.mbarrier::complete_tx::bytes "
                     "[%0], [%1], %2, [%3];"
                     :: "r"(smem_buf), "l"(rg + (size_t)idx0 * 19),
                        "r"((uint32_t)RG_BYTES), "r"(smem_mbar) : "memory");
    }

    // ---- cam computation (overlaps DMA) ----
    if (tid == 0) {
        const float* E = ext + b * 16;
        const float* K = intr + b * 9;
#pragma unroll
        for (int i = 0; i < 3; i++) {
            cam.c2w[i * 3 + 0] = E[i * 4 + 0];
            cam.c2w[i * 3 + 1] = E[i * 4 + 1];
            cam.c2w[i * 3 + 2] = E[i * 4 + 2];
            cam.t[i]           = E[i * 4 + 3];
        }
        float k00 = K[0], k01 = K[1], k02 = K[2];
        float k10 = K[3], k11 = K[4], k12 = K[5];
        float k20 = K[6], k21 = K[7], k22 = K[8];
        float det = k00 * (k11 * k22 - k12 * k21)
                  - k01 * (k10 * k22 - k12 * k20)
                  + k02 * (k10 * k21 - k11 * k20);
        float id = 1.0f / det;
        cam.Kinv[0] = (k11 * k22 - k12 * k21) * id;
        cam.Kinv[1] = (k02 * k21 - k01 * k22) * id;
        cam.Kinv[2] = (k01 * k12 - k02 * k11) * id;
        cam.Kinv[3] = (k12 * k20 - k10 * k22) * id;
        cam.Kinv[4] = (k00 * k22 - k02 * k20) * id;
        cam.Kinv[5] = (k02 * k10 - k00 * k12) * id;
        cam.Kinv[6] = (k10 * k21 - k11 * k20) * id;
        cam.Kinv[7] = (k01 * k20 - k00 * k21) * id;
        cam.Kinv[8] = (k00 * k11 - k01 * k10) * id;

        unsigned hv = hptr[0], wv = wptr[0];
        float hf = (hv < 100000u) ? (float)hv : __uint_as_float(hv);
        float wf = (wv < 100000u) ? (float)wv : __uint_as_float(wv);
        float px = 1.0f / wf, py = 1.0f / hf;
        float det2 = k00 * k11 - k01 * k10;
        cam.mult = 0.1f * ((k11 * px - k01 * py) + (-k10 * px + k00 * py)) / det2;
    }

    // ---- per-thread scalar inputs (LDGs overlap the DMA) ----
    float2 uv = make_float2(0.f, 0.f);
    float depth = 0.f, op = 0.f;
    if (live) {
        uv    = ((const float2*)coords)[idx];
        depth = depths[idx];
        op    = opac[idx];
    }

    __syncthreads();   // cam ready (also orders mbar init for all threads)

    // ---- output section pointers ----
    float* means_o = out;                 // BN*3
    float* cov_o   = out + BN * 3;        // BN*9
    float* har_o   = out + BN * 12;       // BN*12
    float* op_o    = out + BN * 24;       // BN*1
    float* sc_o    = out + BN * 25;       // BN*3
    float* rot_o   = out + BN * 28;       // BN*4

    // ---- rg-independent outputs first: opacity + means (hides DMA latency) ----
    if (live) {
        __stcs(op_o + idx, op);

        float d0 = cam.Kinv[0] * uv.x + cam.Kinv[1] * uv.y + cam.Kinv[2];
        float d1 = cam.Kinv[3] * uv.x + cam.Kinv[4] * uv.y + cam.Kinv[5];
        float d2 = cam.Kinv[6] * uv.x + cam.Kinv[7] * uv.y + cam.Kinv[8];
        float rn = rsqrtf(d0 * d0 + d1 * d1 + d2 * d2);
        d0 *= rn; d1 *= rn; d2 *= rn;
#pragma unroll
        for (int i = 0; i < 3; i++)
            __stcs(means_o + (size_t)idx * 3 + i,
                   cam.t[i] + (cam.c2w[i * 3 + 0] * d0
                             + cam.c2w[i * 3 + 1] * d1
                             + cam.c2w[i * 3 + 2] * d2) * depth);
    }

    // ---- wait for the rg tile, then consume ----
    if (full) {
        asm volatile(
            "{\n\t.reg .pred p;\n\t"
            "WAIT_%=:\n\t"
            "mbarrier.try_wait.parity.acquire.cta.shared::cta.b64 p, [%0], %1, 0x989680;\n\t"
            "@p bra DONE_%=;\n\t"
            "bra WAIT_%=;\n\t"
            "DONE_%=:\n\t}"
            :: "r"(smem_mbar), "r"(0u) : "memory");
    }

    float g0, g1, g2, qw, qx, qy, qz;
    const float* grow_s = buf + tid * 19;                 // smem row (full blocks)
    const float* grow_g = rg + (size_t)idx * 19;          // gmem row (tail blocks)
    if (full) {
        g0 = grow_s[0]; g1 = grow_s[1]; g2 = grow_s[2];
        qw = grow_s[3]; qx = grow_s[4]; qy = grow_s[5]; qz = grow_s[6];
    } else if (live) {
        g0 = grow_g[0]; g1 = grow_g[1]; g2 = grow_g[2];
        qw = grow_g[3]; qx = grow_g[4]; qy = grow_g[5]; qz = grow_g[6];
    } else {
        g0 = g1 = g2 = 0.f; qw = 1.f; qx = qy = qz = 0.f;
    }

    // ---- scales ----
    float dm = depth * cam.mult;
    float sc0 = (0.5f + 14.5f / (1.0f + __expf(-g0))) * dm;
    float sc1 = (0.5f + 14.5f / (1.0f + __expf(-g1))) * dm;
    float sc2 = (0.5f + 14.5f / (1.0f + __expf(-g2))) * dm;

    // ---- quaternion normalize ----
    float qn = sqrtf(qw * qw + qx * qx + qy * qy + qz * qz) + 1e-8f;
    float qinv = 1.0f / qn;
    qw *= qinv; qx *= qinv; qy *= qinv; qz *= qinv;

    // ---- harmonics -> registers ----
    float har[12];
    {
        const int pr[3] = {1, 2, 0};
#pragma unroll
        for (int c = 0; c < 3; c++) {
            float h0, s1, s2, s3;
            if (full) {
                h0 = grow_s[7 + c * 4 + 0];
                s1 = grow_s[7 + c * 4 + 1] * 0.025f;
                s2 = grow_s[7 + c * 4 + 2] * 0.025f;
                s3 = grow_s[7 + c * 4 + 3] * 0.025f;
            } else if (live) {
                h0 = grow_g[7 + c * 4 + 0];
                s1 = grow_g[7 + c * 4 + 1] * 0.025f;
                s2 = grow_g[7 + c * 4 + 2] * 0.025f;
                s3 = grow_g[7 + c * 4 + 3] * 0.025f;
            } else {
                h0 = s1 = s2 = s3 = 0.f;
            }
            har[c * 4 + 0] = h0;
#pragma unroll
            for (int i = 0; i < 3; i++) {
                int ri = pr[i];
                har[c * 4 + 1 + i] = cam.c2w[ri * 3 + 1] * s1
                                   + cam.c2w[ri * 3 + 2] * s2
                                   + cam.c2w[ri * 3 + 0] * s3;
            }
        }
    }

    // ---- direct streaming stores: rotations, scales ----
    if (live) {
        __stcs((float4*)rot_o + idx, make_float4(qw, qx, qy, qz));
        __stcs(sc_o + (size_t)idx * 3 + 0, sc0);
        __stcs(sc_o + (size_t)idx * 3 + 1, sc1);
        __stcs(sc_o + (size_t)idx * 3 + 2, sc2);
    }

    // ---- cov = (W R diag(s)) (W R diag(s))^T ----
    float R[9];
    R[0] = 1.f - 2.f * (qy * qy + qz * qz);
    R[1] = 2.f * (qx * qy - qw * qz);
    R[2] = 2.f * (qx * qz + qw * qy);
    R[3] = 2.f * (qx * qy + qw * qz);
    R[4] = 1.f - 2.f * (qx * qx + qz * qz);
    R[5] = 2.f * (qy * qz - qw * qx);
    R[6] = 2.f * (qx * qz - qw * qy);
    R[7] = 2.f * (qy * qz + qw * qx);
    R[8] = 1.f - 2.f * (qx * qx + qy * qy);

    float T[9];
#pragma unroll
    for (int i = 0; i < 3; i++) {
        T[i * 3 + 0] = (cam.c2w[i * 3 + 0] * R[0] + cam.c2w[i * 3 + 1] * R[3]
                      + cam.c2w[i * 3 + 2] * R[6]) * sc0;
        T[i * 3 + 1] = (cam.c2w[i * 3 + 0] * R[1] + cam.c2w[i * 3 + 1] * R[4]
                      + cam.c2w[i * 3 + 2] * R[7]) * sc1;
        T[i * 3 + 2] = (cam.c2w[i * 3 + 0] * R[2] + cam.c2w[i * 3 + 1] * R[5]
                      + cam.c2w[i * 3 + 2] * R[8]) * sc2;
    }
    float cov[9];
#pragma unroll
    for (int i = 0; i < 3; i++)
#pragma unroll
        for (int j = 0; j <= i; j++) {
            float v = T[i * 3 + 0] * T[j * 3 + 0]
                    + T[i * 3 + 1] * T[j * 3 + 1]
                    + T[i * 3 + 2] * T[j * 3 + 2];
            cov[i * 3 + j] = v;
            cov[j * 3 + i] = v;
        }

    if (full) {
        __syncthreads();   // all smem input reads complete; safe to overwrite buf

        // stage cov (scalar, stride 9 odd -> conflict-free)
#pragma unroll
        for (int i = 0; i < 9; i++) buf[tid * 9 + i] = cov[i];
        // stage har (STS.128, float4-stride 3 -> conflict-free)
        {
            float4* h4 = (float4*)(buf + 9 * TPB);
#pragma unroll
            for (int c = 0; c < 3; c++)
                h4[tid * 3 + c] = make_float4(har[c * 4 + 0], har[c * 4 + 1],
                                              har[c * 4 + 2], har[c * 4 + 3]);
        }
        __syncthreads();   // staging complete across the block

        // ---- bulk smem->global flush (TMA path; no per-thread LDS/STG) ----
        if (tid == 0) {
            asm volatile("fence.proxy.async.shared::cta;" ::: "memory");
            asm volatile("cp.async.bulk.global.shared::cta.bulk_group [%0], [%1], %2;"
                         :: "l"(cov_o + (size_t)idx0 * 9), "r"(smem_buf),
                            "r"((uint32_t)COV_BYTES) : "memory");
            asm volatile("cp.async.bulk.global.shared::cta.bulk_group [%0], [%1], %2;"
                         :: "l"(har_o + (size_t)idx0 * 12),
                            "r"(smem_buf + (uint32_t)COV_BYTES),
                            "r"((uint32_t)HAR_BYTES) : "memory");
            asm volatile("cp.async.bulk.commit_group;" ::: "memory");
            // .read: only wait until SMEM reads are done (global writes drain on their own)
            asm volatile("cp.async.bulk.wait_group.read 0;" ::: "memory");
        }
    } else if (live) {
#pragma unroll
        for (int i = 0; i < 9; i++)  __stcs(cov_o + (size_t)idx * 9 + i, cov[i]);
#pragma unroll
        for (int i = 0; i < 12; i++) __stcs(har_o + (size_t)idx * 12 + i, har[i]);
    }
}

extern "C" void kernel_launch(void* const* d_in, const int* in_sizes, int n_in,
                              void* d_out, int out_size)
{
    const float* ext    = (const float*)d_in[0];
    const float* intr   = (const float*)d_in[1];
    const float* coords = (const float*)d_in[2];
    const float* depths = (const float*)d_in[3];
    const float* opac   = (const float*)d_in[4];
    const float* rg     = (const float*)d_in[5];
    const unsigned int* hptr = (const unsigned int*)d_in[6];
    const unsigned int* wptr = (const unsigned int*)d_in[7];
    float* out = (float*)d_out;

    const int B = in_sizes[0] / 16;            // extrinsics: B*1*4*4
    const int N = in_sizes[3] / B;             // depths: B*N

    dim3 grid((N + TPB - 1) / TPB, B);
    mono_gaussian_adapter_kernel<<<grid, TPB>>>(
        ext, intr, coords, depths, opac, rg, hptr, wptr, out, N);
}